// round 10
// baseline (speedup 1.0000x reference)
#include <cuda_runtime.h>
#include <cuda_bf16.h>
#include <mma.h>
#include <cstdint>
#include <cstddef>

using namespace nvcuda;

// Problem constants (fixed by setup_inputs)
#define BB   8
#define LL   4096
#define DD   1024
#define HH   16
#define MROWS (BB * LL)          // 32768

// ---------------------------------------------------------------------------
// Scratch (allocation-free rule: __device__ globals)
// ---------------------------------------------------------------------------
__device__ __align__(1024) float g_xq[(size_t)MROWS * DD];
__device__ __align__(1024) float g_xk[(size_t)MROWS * DD];
__device__ __align__(1024) float g_xv[(size_t)MROWS * DD];
// bf16 split operands: A hi/lo row-major [32768][1024]
__device__ __align__(1024) __nv_bfloat16 g_Ah[(size_t)MROWS * DD];
__device__ __align__(1024) __nv_bfloat16 g_Al[(size_t)MROWS * DD];
// W transposed hi/lo: Bt[n][k] = W[k][n], row-major [1024][1024], 4 matrices
__device__ __align__(1024) __nv_bfloat16 g_Wh[4][(size_t)DD * DD];
__device__ __align__(1024) __nv_bfloat16 g_Wl[4][(size_t)DD * DD];

// ---------------------------------------------------------------------------
// Helpers
// ---------------------------------------------------------------------------
__device__ __forceinline__ uint32_t smem_to_u32(const void* p) {
    uint32_t a;
    asm("{ .reg .u64 t; cvta.to.shared.u64 t, %1; cvt.u32.u64 %0, t; }"
        : "=r"(a) : "l"(p));
    return a;
}
__device__ __forceinline__ void cp_async16(uint32_t dst, const void* src) {
    asm volatile("cp.async.cg.shared.global [%0], [%1], 16;"
                 :: "r"(dst), "l"(src) : "memory");
}
__device__ __forceinline__ void cp_commit() {
    asm volatile("cp.async.commit_group;" ::: "memory");
}
template <int N>
__device__ __forceinline__ void cp_wait() {
    asm volatile("cp.async.wait_group %0;" :: "n"(N) : "memory");
}

__device__ __forceinline__ void split_bf16(float x, __nv_bfloat16& h, __nv_bfloat16& l) {
    h = __float2bfloat16_rn(x);
    l = __float2bfloat16_rn(x - __bfloat162float(h));
}

// ---------------------------------------------------------------------------
// Convert A (fp32 [32768,1024]) -> hi/lo bf16 row-major. 8 floats/thread.
// ---------------------------------------------------------------------------
__global__ __launch_bounds__(256)
void conv_a_kernel(const float4* __restrict__ A,
                   __nv_bfloat16* __restrict__ Hi,
                   __nv_bfloat16* __restrict__ Lo) {
    size_t i = (size_t)blockIdx.x * 256 + threadIdx.x;   // 8-float group index
    float4 x0 = A[i * 2];
    float4 x1 = A[i * 2 + 1];
    float xs[8] = {x0.x, x0.y, x0.z, x0.w, x1.x, x1.y, x1.z, x1.w};
    __nv_bfloat16 h[8], l[8];
#pragma unroll
    for (int j = 0; j < 8; ++j) split_bf16(xs[j], h[j], l[j]);
    *(uint4*)(Hi + i * 8) = *(const uint4*)h;
    *(uint4*)(Lo + i * 8) = *(const uint4*)l;
}

// ---------------------------------------------------------------------------
// Convert + transpose W (fp32 [1024,1024]) -> Bt hi/lo [n][k] bf16.
// ---------------------------------------------------------------------------
__global__ __launch_bounds__(256)
void conv_w_kernel(const float* __restrict__ W,
                   __nv_bfloat16* __restrict__ Hi,
                   __nv_bfloat16* __restrict__ Lo) {
    __shared__ float t[32][33];
    const int tx = threadIdx.x & 31;
    const int ty = threadIdx.x >> 5;        // 0..7
    const int n0 = blockIdx.x * 32, k0 = blockIdx.y * 32;
#pragma unroll
    for (int j = 0; j < 4; ++j)
        t[ty + 8 * j][tx] = W[(size_t)(k0 + ty + 8 * j) * DD + n0 + tx];
    __syncthreads();
#pragma unroll
    for (int j = 0; j < 4; ++j) {
        float v = t[tx][ty + 8 * j];        // = W[k0+tx][n0+ty+8j]
        __nv_bfloat16 h, l;
        split_bf16(v, h, l);
        size_t o = (size_t)(n0 + ty + 8 * j) * DD + k0 + tx;
        Hi[o] = h;
        Lo[o] = l;
    }
}

// ---------------------------------------------------------------------------
// wmma bf16 GEMM (3-pass hi/lo split): C = A @ W + bias.
// BM=BN=128, BK=32, 8 warps (4m x 2n), warp tile 32x64 (2x4 wmma frags).
// 2-stage cp.async pipeline. Smem rows padded to 56 bf16 = 112B (7x16B):
// LDSM row addresses hit 7r mod 8 = all-distinct banks -> conflict-free,
// and 112B row stride keeps every cp.async dst 16B-aligned.
// ---------------------------------------------------------------------------
#define PAD         56
#define IMG_ELEMS   (128 * PAD)             // 7168 bf16 per matrix image
#define IMG_BYTES   (IMG_ELEMS * 2)         // 14336
#define STAGE_BYTES (4 * IMG_BYTES)         // 57344
#define GEMM_SMEM   (2 * STAGE_BYTES)       // 114688 (epilogue reuses it)

__global__ __launch_bounds__(256, 2)
void gemm_wmma_kernel(const __nv_bfloat16* __restrict__ Ah,
                      const __nv_bfloat16* __restrict__ Al,
                      const __nv_bfloat16* __restrict__ Bh,
                      const __nv_bfloat16* __restrict__ Bl,
                      const float* __restrict__ bias,
                      float* __restrict__ C) {
    extern __shared__ __align__(128) uint8_t smem[];
    const uint32_t sb = smem_to_u32(smem);
    const int tid = threadIdx.x;
    const int wid = tid >> 5;
    const int wm = wid & 3;                 // 0..3 -> 32-row strip
    const int wn = wid >> 2;                // 0..1 -> 64-col strip
    const int nt = blockIdx.x, mt = blockIdx.y;
    const int row0 = mt * 128, col0 = nt * 128;

    wmma::fragment<wmma::accumulator, 16, 16, 16, float> acc[2][4];
#pragma unroll
    for (int i = 0; i < 2; ++i)
#pragma unroll
        for (int j = 0; j < 4; ++j) wmma::fill_fragment(acc[i][j], 0.0f);

#define LOAD_STAGE(t, s) do {                                               \
    const int k0 = (t) * 32;                                                \
    uint32_t st = sb + (uint32_t)(s) * STAGE_BYTES;                         \
    _Pragma("unroll")                                                       \
    for (int h = 0; h < 2; ++h) {                                           \
        int c   = tid + h * 256;            /* 0..511 */                    \
        int row = c >> 2;                   /* 0..127 */                    \
        int q   = (c & 3) * 8;              /* k offset 0,8,16,24 */        \
        uint32_t doff = (uint32_t)(row * PAD + q) * 2;                      \
        size_t aoff = (size_t)(row0 + row) * DD + k0 + q;                   \
        size_t boff = (size_t)(col0 + row) * DD + k0 + q;                   \
        cp_async16(st + doff,                           Ah + aoff);         \
        cp_async16(st + (uint32_t)IMG_BYTES + doff,     Al + aoff);         \
        cp_async16(st + (uint32_t)(2 * IMG_BYTES) + doff, Bh + boff);       \
        cp_async16(st + (uint32_t)(3 * IMG_BYTES) + doff, Bl + boff);       \
    }                                                                       \
} while (0)

    LOAD_STAGE(0, 0);
    cp_commit();

    for (int t = 0; t < 32; ++t) {
        const int s = t & 1;
        if (t + 1 < 32) {
            LOAD_STAGE(t + 1, s ^ 1);
            cp_commit();
            cp_wait<1>();
        } else {
            cp_wait<0>();
        }
        __syncthreads();

        const __nv_bfloat16* sAh = (const __nv_bfloat16*)(smem + s * STAGE_BYTES);
        const __nv_bfloat16* sAl = sAh + IMG_ELEMS;
        const __nv_bfloat16* sBh = sAh + 2 * IMG_ELEMS;
        const __nv_bfloat16* sBl = sAh + 3 * IMG_ELEMS;

#pragma unroll
        for (int ks = 0; ks < 2; ++ks) {
            const int ko = ks * 16;
            wmma::fragment<wmma::matrix_a, 16, 16, 16, __nv_bfloat16,
                           wmma::row_major> a_h[2], a_l[2];
#pragma unroll
            for (int i = 0; i < 2; ++i) {
                const int r = (wm * 32 + i * 16) * PAD + ko;
                wmma::load_matrix_sync(a_h[i], sAh + r, PAD);
                wmma::load_matrix_sync(a_l[i], sAl + r, PAD);
            }
#pragma unroll
            for (int j = 0; j < 4; ++j) {
                wmma::fragment<wmma::matrix_b, 16, 16, 16, __nv_bfloat16,
                               wmma::col_major> b_h, b_l;
                const int r = (wn * 64 + j * 16) * PAD + ko;
                wmma::load_matrix_sync(b_h, sBh + r, PAD);
                wmma::load_matrix_sync(b_l, sBl + r, PAD);
#pragma unroll
                for (int i = 0; i < 2; ++i) {
                    wmma::mma_sync(acc[i][j], a_h[i], b_h, acc[i][j]);
                    wmma::mma_sync(acc[i][j], a_h[i], b_l, acc[i][j]);
                    wmma::mma_sync(acc[i][j], a_l[i], b_h, acc[i][j]);
                }
            }
        }
        __syncthreads();
    }
#undef LOAD_STAGE

    // --- epilogue: acc -> smem (128x132 f32) -> coalesced bias-add stores ---
    float* cs = (float*)smem;
#pragma unroll
    for (int i = 0; i < 2; ++i)
#pragma unroll
        for (int j = 0; j < 4; ++j)
            wmma::store_matrix_sync(cs + (wm * 32 + i * 16) * 132 + wn * 64 + j * 16,
                                    acc[i][j], 132, wmma::mem_row_major);
    __syncthreads();

#pragma unroll
    for (int it = 0; it < 16; ++it) {
        int idx = tid + it * 256;            // 4096 float4 groups
        int r   = idx >> 5;                  // 0..127
        int c4  = (idx & 31) * 4;            // 0..124
        float4 bv = *(const float4*)(bias + col0 + c4);
        float4 o;
        o.x = cs[r * 132 + c4 + 0] + bv.x;
        o.y = cs[r * 132 + c4 + 1] + bv.y;
        o.z = cs[r * 132 + c4 + 2] + bv.z;
        o.w = cs[r * 132 + c4 + 3] + bv.w;
        *(float4*)(C + (size_t)(row0 + r) * DD + col0 + c4) = o;
    }
}

// ---------------------------------------------------------------------------
// Head-axis attention. Now emits ctx directly as split hi/lo bf16 (feeds the
// output-projection GEMM without a conv_a pass or fp32 round-trip).
// ---------------------------------------------------------------------------
__global__ __launch_bounds__(256)
void attn_kernel(const float4* __restrict__ Xq,
                 const float4* __restrict__ Xk,
                 const float4* __restrict__ Xv,
                 __nv_bfloat16* __restrict__ CtxH,
                 __nv_bfloat16* __restrict__ CtxL,
                 float4* __restrict__ Wout) {
    const int g = blockIdx.x;
    const int b = blockIdx.y;

    extern __shared__ float sm[];
    float4* Qs = (float4*)sm;
    float4* Ks = Qs + 4096;
    float4* Vs = Ks + 4096;
    float*  Ws = (float*)(Vs + 4096);

    const int tid = threadIdx.x;

    for (int i = tid; i < 4096; i += 256) {
        int h  = i >> 8;
        int cv = i & 255;
        size_t gi = ((size_t)(b * LL + h * 256 + g)) * 256 + cv;
        Qs[i] = Xq[gi];
        Ks[i] = Xk[gi];
        Vs[i] = Xv[gi];
    }
    __syncthreads();

    const int c  = tid >> 4;
    const int hh = tid & 15;

    float4 qr[16];
#pragma unroll
    for (int e = 0; e < 16; ++e) qr[e] = Qs[hh * 256 + c * 16 + e];

    float s[16];
#pragma unroll
    for (int j = 0; j < 16; ++j) {
        float acc = 0.f;
#pragma unroll
        for (int e = 0; e < 16; ++e) {
            float4 kv = Ks[j * 256 + c * 16 + e];
            acc += qr[e].x * kv.x + qr[e].y * kv.y + qr[e].z * kv.z + qr[e].w * kv.w;
        }
        s[j] = acc * 0.125f;
    }

    float m = s[0];
#pragma unroll
    for (int j = 1; j < 16; ++j) m = fmaxf(m, s[j]);
    float sum = 0.f;
#pragma unroll
    for (int j = 0; j < 16; ++j) { s[j] = expf(s[j] - m); sum += s[j]; }
    float inv = 1.f / sum;
#pragma unroll
    for (int j = 0; j < 16; ++j) s[j] *= inv;

#pragma unroll
    for (int j = 0; j < 16; ++j) Ws[(c * 16 + hh) * 16 + j] = s[j];

    {
        float4* wp = Wout + ((size_t)((b * LL + g * 16 + c) * 16 + hh)) * 4;
        wp[0] = make_float4(s[0],  s[1],  s[2],  s[3]);
        wp[1] = make_float4(s[4],  s[5],  s[6],  s[7]);
        wp[2] = make_float4(s[8],  s[9],  s[10], s[11]);
        wp[3] = make_float4(s[12], s[13], s[14], s[15]);
    }
    __syncthreads();

    const int sidx = hh;
    float4 vr[16];
#pragma unroll
    for (int j = 0; j < 16; ++j) vr[j] = Vs[j * 256 + c * 16 + sidx];

#pragma unroll
    for (int h2 = 0; h2 < 16; ++h2) {
        float4 acc = make_float4(0.f, 0.f, 0.f, 0.f);
#pragma unroll
        for (int j = 0; j < 16; ++j) {
            float w = Ws[(c * 16 + h2) * 16 + j];
            acc.x += w * vr[j].x;
            acc.y += w * vr[j].y;
            acc.z += w * vr[j].z;
            acc.w += w * vr[j].w;
        }
        // Split to hi/lo bf16 and store (4 elems = 8B each)
        __nv_bfloat16 hv[4], lv[4];
        split_bf16(acc.x, hv[0], lv[0]);
        split_bf16(acc.y, hv[1], lv[1]);
        split_bf16(acc.z, hv[2], lv[2]);
        split_bf16(acc.w, hv[3], lv[3]);
        size_t eo = ((size_t)(b * LL + h2 * 256 + g)) * 1024 + c * 64 + sidx * 4;
        *(uint2*)(CtxH + eo) = *(const uint2*)hv;
        *(uint2*)(CtxL + eo) = *(const uint2*)lv;
    }
}

// ---------------------------------------------------------------------------
// Launch sequence
// ---------------------------------------------------------------------------
extern "C" void kernel_launch(void* const* d_in, const int* in_sizes, int n_in,
                              void* d_out, int out_size) {
    const float* q  = (const float*)d_in[0];
    const float* k  = (const float*)d_in[1];
    const float* v  = (const float*)d_in[2];
    const float* Wq = (const float*)d_in[3];
    const float* bq = (const float*)d_in[4];
    const float* Wk = (const float*)d_in[5];
    const float* bk = (const float*)d_in[6];
    const float* Wv = (const float*)d_in[7];
    const float* bv = (const float*)d_in[8];
    const float* Wo = (const float*)d_in[9];
    const float* bo = (const float*)d_in[10];

    float* out = (float*)d_out;
    float* wts = out + (size_t)MROWS * DD;

    float *xq, *xk, *xv;
    __nv_bfloat16 *ah, *al, *wh, *wl;
    cudaGetSymbolAddress((void**)&xq,  g_xq);
    cudaGetSymbolAddress((void**)&xk,  g_xk);
    cudaGetSymbolAddress((void**)&xv,  g_xv);
    cudaGetSymbolAddress((void**)&ah,  g_Ah);
    cudaGetSymbolAddress((void**)&al,  g_Al);
    cudaGetSymbolAddress((void**)&wh,  g_Wh);
    cudaGetSymbolAddress((void**)&wl,  g_Wl);

    const size_t WSZ = (size_t)DD * DD;
    __nv_bfloat16* wh4[4] = {wh, wh + WSZ, wh + 2 * WSZ, wh + 3 * WSZ};
    __nv_bfloat16* wl4[4] = {wl, wl + WSZ, wl + 2 * WSZ, wl + 3 * WSZ};
    const float* Ws4[4] = {Wq, Wk, Wv, Wo};

    const int ATTN_SMEM = (3 * 4096 * 16) + (4096 * 4);
    cudaFuncSetAttribute(attn_kernel,
                         cudaFuncAttributeMaxDynamicSharedMemorySize, ATTN_SMEM);
    cudaFuncSetAttribute(gemm_wmma_kernel,
                         cudaFuncAttributeMaxDynamicSharedMemorySize, GEMM_SMEM);

    dim3 gW(32, 32);                         // conv_w: 32x32 tiles
    dim3 gA(MROWS * DD / 8 / 256);           // conv_a: 16384 blocks
    dim3 gG(8, 256);                         // gemm: 8 n-tiles x 256 m-tiles
    dim3 gAt(LL / 16, BB);

    for (int i = 0; i < 4; ++i)
        conv_w_kernel<<<gW, 256>>>(Ws4[i], wh4[i], wl4[i]);

    conv_a_kernel<<<gA, 256>>>((const float4*)q, ah, al);
    gemm_wmma_kernel<<<gG, 256, GEMM_SMEM>>>(ah, al, wh4[0], wl4[0], bq, xq);

    conv_a_kernel<<<gA, 256>>>((const float4*)k, ah, al);
    gemm_wmma_kernel<<<gG, 256, GEMM_SMEM>>>(ah, al, wh4[1], wl4[1], bk, xk);

    conv_a_kernel<<<gA, 256>>>((const float4*)v, ah, al);
    gemm_wmma_kernel<<<gG, 256, GEMM_SMEM>>>(ah, al, wh4[2], wl4[2], bv, xv);

    // attention writes ctx directly as split bf16 into ah/al
    attn_kernel<<<gAt, 256, ATTN_SMEM>>>((const float4*)xq, (const float4*)xk,
                                         (const float4*)xv, ah, al,
                                         (float4*)wts);

    gemm_wmma_kernel<<<gG, 256, GEMM_SMEM>>>(ah, al, wh4[3], wl4[3], bo, out);
}

// round 11
// speedup vs baseline: 1.0872x; 1.0872x over previous
#include <cuda_runtime.h>
#include <cuda_bf16.h>
#include <mma.h>
#include <cstdint>
#include <cstddef>

using namespace nvcuda;

// Problem constants (fixed by setup_inputs)
#define BB   8
#define LL   4096
#define DD   1024
#define HH   16
#define MROWS (BB * LL)          // 32768

// ---------------------------------------------------------------------------
// Scratch (allocation-free rule: __device__ globals)
// ---------------------------------------------------------------------------
__device__ __align__(1024) float g_xq[(size_t)MROWS * DD];
__device__ __align__(1024) float g_xk[(size_t)MROWS * DD];
__device__ __align__(1024) float g_xv[(size_t)MROWS * DD];
// bf16 split operands: A hi/lo row-major [32768][1024]
__device__ __align__(1024) __nv_bfloat16 g_Ah[(size_t)MROWS * DD];
__device__ __align__(1024) __nv_bfloat16 g_Al[(size_t)MROWS * DD];
// W transposed hi/lo: Bt[n][k] = W[k][n], row-major [1024][1024], 4 matrices
__device__ __align__(1024) __nv_bfloat16 g_Wh[4][(size_t)DD * DD];
__device__ __align__(1024) __nv_bfloat16 g_Wl[4][(size_t)DD * DD];

// ---------------------------------------------------------------------------
// Helpers
// ---------------------------------------------------------------------------
__device__ __forceinline__ uint32_t smem_to_u32(const void* p) {
    uint32_t a;
    asm("{ .reg .u64 t; cvta.to.shared.u64 t, %1; cvt.u32.u64 %0, t; }"
        : "=r"(a) : "l"(p));
    return a;
}
__device__ __forceinline__ void cp_async16(uint32_t dst, const void* src) {
    asm volatile("cp.async.cg.shared.global [%0], [%1], 16;"
                 :: "r"(dst), "l"(src) : "memory");
}
__device__ __forceinline__ void cp_commit() {
    asm volatile("cp.async.commit_group;" ::: "memory");
}
template <int N>
__device__ __forceinline__ void cp_wait() {
    asm volatile("cp.async.wait_group %0;" :: "n"(N) : "memory");
}

__device__ __forceinline__ void split_bf16(float x, __nv_bfloat16& h, __nv_bfloat16& l) {
    h = __float2bfloat16_rn(x);
    l = __float2bfloat16_rn(x - __bfloat162float(h));
}

// ---------------------------------------------------------------------------
// Convert A (fp32 [32768,1024]) -> hi/lo bf16 row-major. 8 floats/thread.
// ---------------------------------------------------------------------------
__global__ __launch_bounds__(256)
void conv_a_kernel(const float4* __restrict__ A,
                   __nv_bfloat16* __restrict__ Hi,
                   __nv_bfloat16* __restrict__ Lo) {
    size_t i = (size_t)blockIdx.x * 256 + threadIdx.x;   // 8-float group index
    float4 x0 = A[i * 2];
    float4 x1 = A[i * 2 + 1];
    float xs[8] = {x0.x, x0.y, x0.z, x0.w, x1.x, x1.y, x1.z, x1.w};
    __nv_bfloat16 h[8], l[8];
#pragma unroll
    for (int j = 0; j < 8; ++j) split_bf16(xs[j], h[j], l[j]);
    *(uint4*)(Hi + i * 8) = *(const uint4*)h;
    *(uint4*)(Lo + i * 8) = *(const uint4*)l;
}

// ---------------------------------------------------------------------------
// Convert + transpose W (fp32 [1024,1024]) -> Bt hi/lo [n][k] bf16.
// ---------------------------------------------------------------------------
__global__ __launch_bounds__(256)
void conv_w_kernel(const float* __restrict__ W,
                   __nv_bfloat16* __restrict__ Hi,
                   __nv_bfloat16* __restrict__ Lo) {
    __shared__ float t[32][33];
    const int tx = threadIdx.x & 31;
    const int ty = threadIdx.x >> 5;        // 0..7
    const int n0 = blockIdx.x * 32, k0 = blockIdx.y * 32;
#pragma unroll
    for (int j = 0; j < 4; ++j)
        t[ty + 8 * j][tx] = W[(size_t)(k0 + ty + 8 * j) * DD + n0 + tx];
    __syncthreads();
#pragma unroll
    for (int j = 0; j < 4; ++j) {
        float v = t[tx][ty + 8 * j];        // = W[k0+tx][n0+ty+8j]
        __nv_bfloat16 h, l;
        split_bf16(v, h, l);
        size_t o = (size_t)(n0 + ty + 8 * j) * DD + k0 + tx;
        Hi[o] = h;
        Lo[o] = l;
    }
}

// ---------------------------------------------------------------------------
// wmma bf16 GEMM (3-pass hi/lo split): C = A @ W + bias.
// BM=BN=128, BK=32, 8 warps (4m x 2n), warp tile 32x64 (2x4 wmma frags).
// 2-stage cp.async pipeline. PAD=48 (R9 empirically-best layout).
// ---------------------------------------------------------------------------
#define PAD         48
#define IMG_ELEMS   (128 * PAD)             // 6144 bf16 per matrix image
#define IMG_BYTES   (IMG_ELEMS * 2)         // 12288
#define STAGE_BYTES (4 * IMG_BYTES)         // 49152
#define GEMM_SMEM   (2 * STAGE_BYTES)       // 98304 (epilogue reuses it)

__global__ __launch_bounds__(256, 2)
void gemm_wmma_kernel(const __nv_bfloat16* __restrict__ Ah,
                      const __nv_bfloat16* __restrict__ Al,
                      const __nv_bfloat16* __restrict__ Bh,
                      const __nv_bfloat16* __restrict__ Bl,
                      const float* __restrict__ bias,
                      float* __restrict__ C) {
    extern __shared__ __align__(128) uint8_t smem[];
    const uint32_t sb = smem_to_u32(smem);
    const int tid = threadIdx.x;
    const int wid = tid >> 5;
    const int wm = wid & 3;                 // 0..3 -> 32-row strip
    const int wn = wid >> 2;                // 0..1 -> 64-col strip
    const int nt = blockIdx.x, mt = blockIdx.y;
    const int row0 = mt * 128, col0 = nt * 128;

    wmma::fragment<wmma::accumulator, 16, 16, 16, float> acc[2][4];
#pragma unroll
    for (int i = 0; i < 2; ++i)
#pragma unroll
        for (int j = 0; j < 4; ++j) wmma::fill_fragment(acc[i][j], 0.0f);

#define LOAD_STAGE(t, s) do {                                               \
    const int k0 = (t) * 32;                                                \
    uint32_t st = sb + (uint32_t)(s) * STAGE_BYTES;                         \
    _Pragma("unroll")                                                       \
    for (int h = 0; h < 2; ++h) {                                           \
        int c   = tid + h * 256;            /* 0..511 */                    \
        int row = c >> 2;                   /* 0..127 */                    \
        int q   = (c & 3) * 8;              /* k offset 0,8,16,24 */        \
        uint32_t doff = (uint32_t)(row * PAD + q) * 2;                      \
        size_t aoff = (size_t)(row0 + row) * DD + k0 + q;                   \
        size_t boff = (size_t)(col0 + row) * DD + k0 + q;                   \
        cp_async16(st + doff,                             Ah + aoff);       \
        cp_async16(st + (uint32_t)IMG_BYTES + doff,       Al + aoff);       \
        cp_async16(st + (uint32_t)(2 * IMG_BYTES) + doff, Bh + boff);       \
        cp_async16(st + (uint32_t)(3 * IMG_BYTES) + doff, Bl + boff);       \
    }                                                                       \
} while (0)

    LOAD_STAGE(0, 0);
    cp_commit();

    for (int t = 0; t < 32; ++t) {
        const int s = t & 1;
        if (t + 1 < 32) {
            LOAD_STAGE(t + 1, s ^ 1);
            cp_commit();
            cp_wait<1>();
        } else {
            cp_wait<0>();
        }
        __syncthreads();

        const __nv_bfloat16* sAh = (const __nv_bfloat16*)(smem + s * STAGE_BYTES);
        const __nv_bfloat16* sAl = sAh + IMG_ELEMS;
        const __nv_bfloat16* sBh = sAh + 2 * IMG_ELEMS;
        const __nv_bfloat16* sBl = sAh + 3 * IMG_ELEMS;

#pragma unroll
        for (int ks = 0; ks < 2; ++ks) {
            const int ko = ks * 16;
            wmma::fragment<wmma::matrix_a, 16, 16, 16, __nv_bfloat16,
                           wmma::row_major> a_h[2], a_l[2];
#pragma unroll
            for (int i = 0; i < 2; ++i) {
                const int r = (wm * 32 + i * 16) * PAD + ko;
                wmma::load_matrix_sync(a_h[i], sAh + r, PAD);
                wmma::load_matrix_sync(a_l[i], sAl + r, PAD);
            }
#pragma unroll
            for (int j = 0; j < 4; ++j) {
                wmma::fragment<wmma::matrix_b, 16, 16, 16, __nv_bfloat16,
                               wmma::col_major> b_h, b_l;
                const int r = (wn * 64 + j * 16) * PAD + ko;
                wmma::load_matrix_sync(b_h, sBh + r, PAD);
                wmma::load_matrix_sync(b_l, sBl + r, PAD);
#pragma unroll
                for (int i = 0; i < 2; ++i) {
                    wmma::mma_sync(acc[i][j], a_h[i], b_h, acc[i][j]);
                    wmma::mma_sync(acc[i][j], a_h[i], b_l, acc[i][j]);
                    wmma::mma_sync(acc[i][j], a_l[i], b_h, acc[i][j]);
                }
            }
        }
        __syncthreads();
    }
#undef LOAD_STAGE

    // --- epilogue: acc -> smem (128x132 f32) -> coalesced bias-add stores ---
    float* cs = (float*)smem;
#pragma unroll
    for (int i = 0; i < 2; ++i)
#pragma unroll
        for (int j = 0; j < 4; ++j)
            wmma::store_matrix_sync(cs + (wm * 32 + i * 16) * 132 + wn * 64 + j * 16,
                                    acc[i][j], 132, wmma::mem_row_major);
    __syncthreads();

#pragma unroll
    for (int it = 0; it < 16; ++it) {
        int idx = tid + it * 256;            // 4096 float4 groups
        int r   = idx >> 5;                  // 0..127
        int c4  = (idx & 31) * 4;            // 0..124
        float4 bv = *(const float4*)(bias + col0 + c4);
        float4 o;
        o.x = cs[r * 132 + c4 + 0] + bv.x;
        o.y = cs[r * 132 + c4 + 1] + bv.y;
        o.z = cs[r * 132 + c4 + 2] + bv.z;
        o.w = cs[r * 132 + c4 + 3] + bv.w;
        *(float4*)(C + (size_t)(row0 + r) * DD + col0 + c4) = o;
    }
}

// ---------------------------------------------------------------------------
// Head-axis attention, occupancy-optimized:
//   - only K staged in smem (64KB; genuinely shared 16-ways)
//   - Q streamed from global, one float4 live at a time (thread-private data)
//   - V loaded direct from global (per-j load is fully coalesced: 32 lanes
//     cover one contiguous 512B row segment)
//   - softmax-weight exchange via __shfl_sync (threads sharing c are in the
//     same warp: lane = (c&1)*16 + hh)
// Emits ctx directly as split hi/lo bf16 for the output-projection GEMM.
// ---------------------------------------------------------------------------
#define ATTN_SMEM (4096 * 16)               // 64KB: K tile as float4

__global__ __launch_bounds__(256, 2)
void attn_kernel(const float4* __restrict__ Xq,
                 const float4* __restrict__ Xk,
                 const float4* __restrict__ Xv,
                 __nv_bfloat16* __restrict__ CtxH,
                 __nv_bfloat16* __restrict__ CtxL,
                 float4* __restrict__ Wout) {
    const int g = blockIdx.x;
    const int b = blockIdx.y;

    extern __shared__ float4 Ks[];          // [16 heads][256 float4]
    const int tid  = threadIdx.x;
    const int lane = tid & 31;

    // Stage K: 16 scattered rows (head h -> global row b*4096 + h*256 + g)
    for (int i = tid; i < 4096; i += 256) {
        int h  = i >> 8;
        int cv = i & 255;
        Ks[i] = Xk[((size_t)(b * LL + h * 256 + g)) * 256 + cv];
    }
    __syncthreads();

    const int c  = tid >> 4;   // position within group (0..15)
    const int hh = tid & 15;   // head row / e-slice

    // ---- Phase 1: s[j] = scale * <Q[hh,c], K[j,c]>, streaming Q from global
    float s[16];
#pragma unroll
    for (int j = 0; j < 16; ++j) s[j] = 0.f;

    const float4* qbase =
        Xq + ((size_t)(b * LL + hh * 256 + g)) * 256 + c * 16;
    float4 qf = qbase[0];
#pragma unroll
    for (int e = 0; e < 16; ++e) {
        float4 qn = qf;
        if (e < 15) qn = qbase[e + 1];       // prefetch next
#pragma unroll
        for (int j = 0; j < 16; ++j) {
            float4 kv = Ks[j * 256 + c * 16 + e];
            s[j] += qf.x * kv.x + qf.y * kv.y + qf.z * kv.z + qf.w * kv.w;
        }
        qf = qn;
    }
#pragma unroll
    for (int j = 0; j < 16; ++j) s[j] *= 0.125f;   // hd^-0.5 = 1/8

    float m = s[0];
#pragma unroll
    for (int j = 1; j < 16; ++j) m = fmaxf(m, s[j]);
    float sum = 0.f;
#pragma unroll
    for (int j = 0; j < 16; ++j) { s[j] = expf(s[j] - m); sum += s[j]; }
    float inv = 1.f / sum;
#pragma unroll
    for (int j = 0; j < 16; ++j) s[j] *= inv;

    // weights -> global, natural (B, L, H, H) layout
    {
        float4* wp = Wout + ((size_t)((b * LL + g * 16 + c) * 16 + hh)) * 4;
        wp[0] = make_float4(s[0],  s[1],  s[2],  s[3]);
        wp[1] = make_float4(s[4],  s[5],  s[6],  s[7]);
        wp[2] = make_float4(s[8],  s[9],  s[10], s[11]);
        wp[3] = make_float4(s[12], s[13], s[14], s[15]);
    }

    // ---- Phase 2: ctx[h2][sidx] = sum_j w[h2][j] * V[j][sidx]
    // V direct from global: per-j instruction covers 512B contiguous.
    const int sidx = hh;
    float4 vr[16];
#pragma unroll
    for (int j = 0; j < 16; ++j)
        vr[j] = Xv[((size_t)(b * LL + j * 256 + g)) * 256 + c * 16 + sidx];

#pragma unroll
    for (int h2 = 0; h2 < 16; ++h2) {
        const int src = (lane & 16) | h2;    // lane of thread (c, hh=h2)
        float4 acc = make_float4(0.f, 0.f, 0.f, 0.f);
#pragma unroll
        for (int j = 0; j < 16; ++j) {
            float w = __shfl_sync(0xffffffffu, s[j], src);
            acc.x += w * vr[j].x;
            acc.y += w * vr[j].y;
            acc.z += w * vr[j].z;
            acc.w += w * vr[j].w;
        }
        __nv_bfloat16 hv[4], lv[4];
        split_bf16(acc.x, hv[0], lv[0]);
        split_bf16(acc.y, hv[1], lv[1]);
        split_bf16(acc.z, hv[2], lv[2]);
        split_bf16(acc.w, hv[3], lv[3]);
        size_t eo = ((size_t)(b * LL + h2 * 256 + g)) * 1024 + c * 64 + sidx * 4;
        *(uint2*)(CtxH + eo) = *(const uint2*)hv;
        *(uint2*)(CtxL + eo) = *(const uint2*)lv;
    }
}

// ---------------------------------------------------------------------------
// Launch sequence
// ---------------------------------------------------------------------------
extern "C" void kernel_launch(void* const* d_in, const int* in_sizes, int n_in,
                              void* d_out, int out_size) {
    const float* q  = (const float*)d_in[0];
    const float* k  = (const float*)d_in[1];
    const float* v  = (const float*)d_in[2];
    const float* Wq = (const float*)d_in[3];
    const float* bq = (const float*)d_in[4];
    const float* Wk = (const float*)d_in[5];
    const float* bk = (const float*)d_in[6];
    const float* Wv = (const float*)d_in[7];
    const float* bv = (const float*)d_in[8];
    const float* Wo = (const float*)d_in[9];
    const float* bo = (const float*)d_in[10];

    float* out = (float*)d_out;
    float* wts = out + (size_t)MROWS * DD;

    float *xq, *xk, *xv;
    __nv_bfloat16 *ah, *al, *wh, *wl;
    cudaGetSymbolAddress((void**)&xq,  g_xq);
    cudaGetSymbolAddress((void**)&xk,  g_xk);
    cudaGetSymbolAddress((void**)&xv,  g_xv);
    cudaGetSymbolAddress((void**)&ah,  g_Ah);
    cudaGetSymbolAddress((void**)&al,  g_Al);
    cudaGetSymbolAddress((void**)&wh,  g_Wh);
    cudaGetSymbolAddress((void**)&wl,  g_Wl);

    const size_t WSZ = (size_t)DD * DD;
    __nv_bfloat16* wh4[4] = {wh, wh + WSZ, wh + 2 * WSZ, wh + 3 * WSZ};
    __nv_bfloat16* wl4[4] = {wl, wl + WSZ, wl + 2 * WSZ, wl + 3 * WSZ};
    const float* Ws4[4] = {Wq, Wk, Wv, Wo};

    cudaFuncSetAttribute(attn_kernel,
                         cudaFuncAttributeMaxDynamicSharedMemorySize, ATTN_SMEM);
    cudaFuncSetAttribute(gemm_wmma_kernel,
                         cudaFuncAttributeMaxDynamicSharedMemorySize, GEMM_SMEM);

    dim3 gW(32, 32);                         // conv_w: 32x32 tiles
    dim3 gA(MROWS * DD / 8 / 256);           // conv_a: 16384 blocks
    dim3 gG(8, 256);                         // gemm: 8 n-tiles x 256 m-tiles
    dim3 gAt(LL / 16, BB);

    for (int i = 0; i < 4; ++i)
        conv_w_kernel<<<gW, 256>>>(Ws4[i], wh4[i], wl4[i]);

    conv_a_kernel<<<gA, 256>>>((const float4*)q, ah, al);
    gemm_wmma_kernel<<<gG, 256, GEMM_SMEM>>>(ah, al, wh4[0], wl4[0], bq, xq);

    conv_a_kernel<<<gA, 256>>>((const float4*)k, ah, al);
    gemm_wmma_kernel<<<gG, 256, GEMM_SMEM>>>(ah, al, wh4[1], wl4[1], bk, xk);

    conv_a_kernel<<<gA, 256>>>((const float4*)v, ah, al);
    gemm_wmma_kernel<<<gG, 256, GEMM_SMEM>>>(ah, al, wh4[2], wl4[2], bv, xv);

    // attention writes ctx directly as split bf16 into ah/al
    attn_kernel<<<gAt, 256, ATTN_SMEM>>>((const float4*)xq, (const float4*)xk,
                                         (const float4*)xv, ah, al,
                                         (float4*)wts);

    gemm_wmma_kernel<<<gG, 256, GEMM_SMEM>>>(ah, al, wh4[3], wl4[3], bo, out);
}